// round 4
// baseline (speedup 1.0000x reference)
#include <cuda_runtime.h>

// HoG layer, fused. 16x16-cell tiles, 128-thread CTAs, 3 cells/thread so
// 36 gather loads are in flight per thread, and 7 CTAs/SM -> all 1024 CTAs
// resident in ONE wave (no tail).
//   input  x: (1, 3, 4096, 4096) f32
//   output feat: (511, 511, 36) f32

#define IMG   4096
#define CELLS 512
#define OUTD  511
#define TC    16          // cells per tile side
#define HW    (TC + 1)    // 17: tile + halo
#define NCELL (HW * HW)   // 289
#define NT    128         // threads per CTA
#define PCELL 3           // cells per thread (3*128 = 384 >= 289)

__global__ __launch_bounds__(NT, 7)
void hog_fused_kernel(const float* __restrict__ x, float* __restrict__ out)
{
    __shared__ float hist[NCELL * 9];   // 2601 floats = 10404 B

    const int cx0 = blockIdx.x * TC;
    const int cy0 = blockIdx.y * TC;
    const int tid = threadIdx.x;
    const long chs = (long)IMG * IMG;   // channel stride

    // Zero the hist slots this thread will fill (same ownership, no barrier).
    #pragma unroll
    for (int it = 0; it < PCELL; it++) {
        const int c = tid + it * NT;
        if (c < NCELL) {
            #pragma unroll
            for (int b = 0; b < 9; b++) hist[c * 9 + b] = 0.0f;
        }
    }

    // ---- Phase 1: PCELL cells per thread, all loads issued up front ----
    const float* base[PCELL];
    bool valid[PCELL], vd[PCELL], vr[PCELL];

    #pragma unroll
    for (int it = 0; it < PCELL; it++) {
        const int c = tid + it * NT;
        const int lcy = c / HW;
        const int lcx = c - lcy * HW;
        const int cy = cy0 + lcy;
        const int cx = cx0 + lcx;
        valid[it] = (c < NCELL) && (cy < CELLS) && (cx < CELLS);
        const int py = cy * 8 + 7;
        const int px = cx * 8 + 7;
        base[it] = x + (long)py * IMG + px;
        vd[it] = valid[it] && (py + 1 < IMG);
        vr[it] = valid[it] && (px + 1 < IMG);
    }

    // Batched predicated gather: up to 36 LDGs in flight.
    float v[PCELL][12];
    #pragma unroll
    for (int it = 0; it < PCELL; it++) {
        const float* p = base[it];
        const bool va = valid[it];
        #pragma unroll
        for (int ch = 0; ch < 3; ch++) {
            const float* pc = p + ch * chs;
            v[it][ch * 4 + 0] = va     ? pc[-IMG] : 0.0f;
            v[it][ch * 4 + 1] = va     ? pc[-1]   : 0.0f;
            v[it][ch * 4 + 2] = vd[it] ? pc[IMG]  : 0.0f;
            v[it][ch * 4 + 3] = vr[it] ? pc[1]    : 0.0f;
        }
    }

    #pragma unroll
    for (int it = 0; it < PCELL; it++) {
        if (!valid[it]) continue;
        const float su = v[it][0] + v[it][4] + v[it][8];
        const float sl = v[it][1] + v[it][5] + v[it][9];
        const float sd = v[it][2] + v[it][6] + v[it][10];
        const float sr = v[it][3] + v[it][7] + v[it][11];

        const float gv = sd - su;
        const float gh = sr - sl;
        const float mag = sqrtf(gv * gv + gh * gh + 1e-6f);
        const float ang = fabsf(atanf(gh / (gv + 1e-9f)))
                          * (180.0f / 3.14159265358979323846f);

        // j = floor(ang/20 - 0.5), ang in [0, 90] -> j in [-1, 4]
        const float t  = ang * 0.05f;
        const int   ji = (int)floorf(t - 0.5f);
        const float vj  = mag * ((float)ji + 1.5f - t);
        const float vj1 = mag - vj;

        const int i0 = (ji < 0) ? 8 : ji;   // mod(ji, 9)
        const int i1 = ji + 1;              // in [0, 5], never == i0
        float* hrow = &hist[(tid + it * NT) * 9];
        hrow[i0] = vj;
        hrow[i1] = vj1;
    }
    __syncthreads();

    // ---- Phase 2: two output blocks per thread, sequentially ----
    #pragma unroll
    for (int k = 0; k < 2; k++) {
        const int o  = tid + k * NT;       // 0..255
        const int ly = o >> 4;
        const int lx = o & 15;
        const int oy = cy0 + ly;
        const int ox = cx0 + lx;
        if (oy >= OUTD || ox >= OUTD) continue;

        const float* h00 = &hist[(ly * HW + lx) * 9];
        const float* h01 = h00 + 9;
        const float* h10 = h00 + HW * 9;
        const float* h11 = h10 + 9;

        float blk[36];
        #pragma unroll
        for (int b = 0; b < 9; b++) {
            blk[b]      = h00[b];
            blk[9  + b] = h01[b];
            blk[18 + b] = h10[b];
            blk[27 + b] = h11[b];
        }

        float ss = 0.f;
        #pragma unroll
        for (int b = 0; b < 36; b++) ss += blk[b] * blk[b];
        const float inv = 1.0f / (sqrtf(ss) + 1e-9f);

        float4* o4 = reinterpret_cast<float4*>(out + ((size_t)oy * OUTD + ox) * 36);
        #pragma unroll
        for (int b = 0; b < 9; b++) {
            o4[b] = make_float4(blk[4 * b + 0] * inv,
                                blk[4 * b + 1] * inv,
                                blk[4 * b + 2] * inv,
                                blk[4 * b + 3] * inv);
        }
    }
}

extern "C" void kernel_launch(void* const* d_in, const int* in_sizes, int n_in,
                              void* d_out, int out_size)
{
    const float* x = (const float*)d_in[0];
    float* out = (float*)d_out;
    dim3 grid(CELLS / TC, CELLS / TC);   // 32 x 32 tiles = 1024 CTAs
    hog_fused_kernel<<<grid, NT>>>(x, out);
}